// round 15
// baseline (speedup 1.0000x reference)
#include <cuda_runtime.h>
#include <math_constants.h>

#define BB 8
#define NN 1024
#define KK 20

typedef unsigned long long ull;

// ---------------- scratch (device globals: no allocation allowed) ----------------
__device__ float d_f0[BB * 3 * NN];            // (B,3,N)
__device__ float d_x1[BB * 21 * 3 * NN];
__device__ float d_x2[BB * 21 * 3 * NN];
__device__ float d_x3[BB * 42 * 3 * NN];
__device__ float d_x4[BB * 85 * 3 * NN];
__device__ int   d_knnIdx[BB * NN * KK];
__device__ float d_sqm[BB * NN];
__device__ float d_pad[BB * NN * 85 * 8 + 16];  // per-point, layout (B,N,O,8): [pa0,da0,pa1,da1,pa2,da2,-,-]
__device__ float d_ctr[BB * NN * 85 * 8 + 16];  // per-point (pb,db) same layout
__device__ float4 d_w4[4998];                   // interleaved [ap,bp,ad,bd] for layers 1..4
__device__ float d_wp5t[169 * 341];
__device__ float d_h5[BB * 1023 * NN];
__device__ float d_g [BB * 2046];
__device__ float d_g1[BB * 512];
__device__ float d_g2[BB * 256];

// ---------------- fused prep: x transpose + Wp5 transpose + w4 table ----------------
__global__ void prep_kernel(const float* __restrict__ x, const float* __restrict__ Wp5,
                            const float* __restrict__ Wp1, const float* __restrict__ Wd1,
                            const float* __restrict__ Wp2, const float* __restrict__ Wd2,
                            const float* __restrict__ Wp3, const float* __restrict__ Wd3,
                            const float* __restrict__ Wp4, const float* __restrict__ Wd4) {
    int i = blockIdx.x * 256 + threadIdx.x;

    if (i < BB * NN * 3) {
        int b = i / (NN * 3);
        int r = i - b * (NN * 3);
        int n = r / 3;
        int j = r - n * 3;
        d_f0[((size_t)b * 3 + j) * NN + n] = x[i];
    }
    if (i < 341 * 169) {
        int o = i / 169, c = i - o * 169;
        d_wp5t[c * 341 + o] = Wp5[i];
    }
    if (i < 4998) {
        const float *Wp, *Wd; int C, Cp, rel;
        if (i < 42)        { Wp = Wp1; Wd = Wd1; C = 1;  Cp = 2;  rel = i; }
        else if (i < 504)  { Wp = Wp2; Wd = Wd2; C = 21; Cp = 22; rel = i - 42; }
        else if (i < 1428) { Wp = Wp3; Wd = Wd3; C = 21; Cp = 22; rel = i - 504; }
        else               { Wp = Wp4; Wd = Wd4; C = 42; Cp = 42; rel = i - 1428; }
        int o = rel / Cp, c = rel - o * Cp;
        float ap = 0.f, bp = 0.f, ad = 0.f, bd = 0.f;
        if (c < C) {
            float wl = Wp[o * 2 * C + c], wr = Wp[o * 2 * C + C + c];
            ap = wl; bp = wr - wl;
            wl = Wd[o * 2 * C + c]; wr = Wd[o * 2 * C + C + c];
            ad = wl; bd = wr - wl;
        }
        d_w4[i] = make_float4(ap, bp, ad, bd);
    }
}

// ---------------- per-point squared norms ----------------
template <int D>
__global__ void __launch_bounds__(256) sq_kernel(const float* __restrict__ feat) {
    int i = blockIdx.x * 256 + threadIdx.x;
    int b = i >> 10, m = i & (NN - 1);
    const float* f = feat + (size_t)b * D * NN + m;
    float s = 0.f;
#pragma unroll 4
    for (int d = 0; d < D; d++) { float v = f[(size_t)d * NN]; s += v * v; }
    d_sqm[i] = s;
}

// ---------------- KNN: warp-local top-20 then single merge ----------------
template <int D>
__global__ void __launch_bounds__(256) knn_kernel(const float* __restrict__ feat) {
    constexpr int NB = 4;
    int b = blockIdx.x / (NN / NB);
    int tile = blockIdx.x % (NN / NB);
    const float* f = feat + (size_t)b * D * NN;

    __shared__ float4 ctr4[D];
    __shared__ ull    lists[NB][8 * KK];

    int t = threadIdx.x, lane = t & 31, wid = t >> 5;
    int nb0 = tile * NB;

    for (int d = t; d < D; d += 256)
        ctr4[d] = make_float4(f[(size_t)d * NN + nb0],     f[(size_t)d * NN + nb0 + 1],
                              f[(size_t)d * NN + nb0 + 2], f[(size_t)d * NN + nb0 + 3]);
    __syncthreads();

    float sqn[NB];
#pragma unroll
    for (int r = 0; r < NB; r++) sqn[r] = d_sqm[b * NN + nb0 + r];
    float4 sq4 = *(const float4*)&d_sqm[b * NN + 4 * t];

    float acc[NB][4];
#pragma unroll
    for (int r = 0; r < NB; r++)
#pragma unroll
        for (int j = 0; j < 4; j++) acc[r][j] = 0.f;

    const float4* fp = (const float4*)(f) + t;
#pragma unroll 4
    for (int d = 0; d < D; d++) {
        float4 v = fp[(size_t)d * (NN / 4)];
        float4 c = ctr4[d];
        acc[0][0] += c.x * v.x; acc[0][1] += c.x * v.y; acc[0][2] += c.x * v.z; acc[0][3] += c.x * v.w;
        acc[1][0] += c.y * v.x; acc[1][1] += c.y * v.y; acc[1][2] += c.y * v.z; acc[1][3] += c.y * v.w;
        acc[2][0] += c.z * v.x; acc[2][1] += c.z * v.y; acc[2][2] += c.z * v.z; acc[2][3] += c.z * v.w;
        acc[3][0] += c.w * v.x; acc[3][1] += c.w * v.y; acc[3][2] += c.w * v.z; acc[3][3] += c.w * v.w;
    }

    ull cand[NB][4];
#pragma unroll
    for (int r = 0; r < NB; r++) {
        float sqj[4] = { sq4.x, sq4.y, sq4.z, sq4.w };
#pragma unroll
        for (int j = 0; j < 4; j++) {
            float dv = 2.f * acc[r][j] - sqn[r] - sqj[j];
            unsigned bits = __float_as_uint(dv);
            unsigned key = (bits & 0x80000000u) ? ~bits : (bits | 0x80000000u);
            int m = 4 * t + j;
            cand[r][j] = ((ull)key << 10) | (unsigned)(1023 - m);
        }
        ull c0 = cand[r][0], c1 = cand[r][1], c2 = cand[r][2], c3 = cand[r][3], tmp;
        if (c1 > c0) { tmp = c0; c0 = c1; c1 = tmp; }
        if (c3 > c2) { tmp = c2; c2 = c3; c3 = tmp; }
        if (c2 > c0) { tmp = c0; c0 = c2; c2 = tmp; }
        if (c3 > c1) { tmp = c1; c1 = c3; c3 = tmp; }
        if (c2 > c1) { tmp = c1; c1 = c2; c2 = tmp; }
        cand[r][0] = c0; cand[r][1] = c1; cand[r][2] = c2; cand[r][3] = c3;
    }

    int ptr[NB] = {0, 0, 0, 0};
    for (int k = 0; k < KK; k++) {
#pragma unroll
        for (int r = 0; r < NB; r++) {
            int p = ptr[r];
            ull h = (p == 0) ? cand[r][0] : (p == 1) ? cand[r][1]
                  : (p == 2) ? cand[r][2] : (p == 3) ? cand[r][3] : 0ULL;
            unsigned hk = (unsigned)(h >> 10);
            unsigned wm = __reduce_max_sync(0xffffffffu, hk);
            unsigned bal = __ballot_sync(0xffffffffu, hk == wm);
            if (lane == __ffs(bal) - 1) {
                lists[r][wid * KK + k] = h;
                ptr[r] = p + 1;
            }
        }
    }
    __syncthreads();

    if (wid < NB) {
        int r = wid;
        ull c5[5];
#pragma unroll
        for (int j = 0; j < 5; j++) c5[j] = lists[r][j * 32 + lane];
        ull tmp;
#define CASD(a, bq) { if (c5[bq] > c5[a]) { tmp = c5[a]; c5[a] = c5[bq]; c5[bq] = tmp; } }
        CASD(0, 1) CASD(3, 4) CASD(2, 4) CASD(2, 3) CASD(1, 4)
        CASD(0, 3) CASD(0, 2) CASD(1, 3) CASD(1, 2)
#undef CASD
        int p = 0;
        size_t ob = ((size_t)b * NN + nb0 + r) * KK;
        for (int k = 0; k < KK; k++) {
            ull h = (p == 0) ? c5[0] : (p == 1) ? c5[1] : (p == 2) ? c5[2]
                  : (p == 3) ? c5[3] : (p == 4) ? c5[4] : 0ULL;
            unsigned hk = (unsigned)(h >> 10);
            unsigned gm = __reduce_max_sync(0xffffffffu, hk);
            unsigned tv = (hk == gm) ? (unsigned)(h & 1023ULL) : 0u;
            unsigned gt = __reduce_max_sync(0xffffffffu, tv);
            unsigned bal = __ballot_sync(0xffffffffu, (hk == gm) && (tv == gt));
            if (lane == __ffs(bal) - 1) {
                d_knnIdx[ob + k] = 1023 - (int)(h & 1023ULL);
                p++;
            }
        }
    }
}

// ---------------- per-point GEMM v2: no smem, uniform LDG.128 weights, o-split ----------------
template <int C, int O, int OG, int WOFF>
__global__ void __launch_bounds__(96) gemm2(const float* __restrict__ x,
                                            float* __restrict__ pad,
                                            float* __restrict__ ctrb) {
    constexpr int Cp = (C + 1) & ~1;
    constexpr int OC = (O + OG - 1) / OG;
    int b = blockIdx.x / (NN / 32);
    int tile = blockIdx.x % (NN / 32);
    int og = blockIdx.y;
    int t = threadIdx.x;
    int n = tile * 32 + (t & 31);
    int ax = t >> 5;

    float xr[Cp];
#pragma unroll
    for (int c = 0; c < C; c++)
        xr[c] = x[(((size_t)b * C + c) * 3 + ax) * NN + n];
    if (Cp > C) xr[Cp - 1] = 0.f;

    int o0 = og * OC;
    int o1 = (o0 + OC < O) ? o0 + OC : O;
    const float4* W4 = d_w4 + WOFF;
    size_t obase = (size_t)(b * NN + n) * (O * 8) + ax * 2;

    for (int o = o0; o < o1; o++) {
        float pa = 0.f, pb = 0.f, da = 0.f, db = 0.f;
#pragma unroll
        for (int cc = 0; cc < Cp; cc += 2) {
            float4 w0 = W4[o * Cp + cc];
            float4 w1 = W4[o * Cp + cc + 1];
            float x0 = xr[cc], x1v = xr[cc + 1];
            pa += w0.x * x0 + w1.x * x1v;
            pb += w0.y * x0 + w1.y * x1v;
            da += w0.z * x0 + w1.z * x1v;
            db += w0.w * x0 + w1.w * x1v;
        }
        *(float2*)&pad[obase + o * 8]  = make_float2(pa, da);
        *(float2*)&ctrb[obase + o * 8] = make_float2(pb, db);
    }
}

// ---------------- edge combine + leaky + learned max-pool (dynamic smem, KC=4) ----------------
template <int O, int OPT, int NP>
__global__ void __launch_bounds__(32 * NP) edge_combine(const float* __restrict__ pad,
                                                        const float* __restrict__ ctrb,
                                                        const float* __restrict__ Wm,
                                                        float* __restrict__ out) {
    constexpr int AT = (O + OPT - 1) / OPT;
    constexpr int Opad = AT * OPT;
    constexpr int KC = 4;
    constexpr int T = 32 * NP;

    extern __shared__ float4 sm4[];
    float4* h4s = sm4;
    float*  WmT = (float*)(sm4 + NP * KC * Opad);
    int*    kk  = (int*)(WmT + O * Opad);

    int b = blockIdx.x / (NN / NP);
    int ptile = blockIdx.x % (NN / NP);
    int t = threadIdx.x;
    int w = t >> 5, lane = t & 31;

    for (int i = t; i < O * O; i += T) {
        int o = i / O, c = i - o * O;
        WmT[c * Opad + o] = Wm[i];
    }
    if constexpr (Opad > O) {
        for (int i = t; i < O * (Opad - O); i += T) {
            int c = i / (Opad - O), j = i - c * (Opad - O);
            WmT[c * Opad + O + j] = 0.f;
        }
    }
    int n = ptile * NP + w;
    if (lane < KK) kk[w * KK + lane] = d_knnIdx[((size_t)b * NN + n) * KK + lane];
    __syncthreads();

    bool act = lane < AT;
    float pb[OPT][3], db[OPT][3];
    size_t cbase = (size_t)(b * NN + n) * (O * 8);
    if (act) {
#pragma unroll
        for (int j = 0; j < OPT; j++) {
            int o = lane * OPT + j;
            float4 u  = *(const float4*)&ctrb[cbase + o * 8];
            float2 u2 = *(const float2*)&ctrb[cbase + o * 8 + 4];
            pb[j][0] = u.x;  db[j][0] = u.y;
            pb[j][1] = u.z;  db[j][1] = u.w;
            pb[j][2] = u2.x; db[j][2] = u2.y;
        }
    }

    float best[OPT];
    float bh[OPT][3];
#pragma unroll
    for (int j = 0; j < OPT; j++) { best[j] = -CUDART_INF_F; bh[j][0] = bh[j][1] = bh[j][2] = 0.f; }

    for (int chunk = 0; chunk < KK / KC; chunk++) {
#pragma unroll
        for (int kc = 0; kc < KC; kc++) {
            int m = kk[w * KK + chunk * KC + kc];
            if (act) {
                size_t gbase = (size_t)(b * NN + m) * (O * 8);
#pragma unroll
                for (int j = 0; j < OPT; j++) {
                    int o = lane * OPT + j;
                    float4 u  = *(const float4*)&pad[gbase + o * 8];
                    float2 u2 = *(const float2*)&pad[gbase + o * 8 + 4];
                    float p0 = u.x  + pb[j][0], q0 = u.y  + db[j][0];
                    float p1 = u.z  + pb[j][1], q1 = u.w  + db[j][1];
                    float p2 = u2.x + pb[j][2], q2 = u2.y + db[j][2];
                    float dot = p0 * q0 + p1 * q1 + p2 * q2;
                    float h0, h1, h2;
                    if (dot >= 0.f) {
                        h0 = p0; h1 = p1; h2 = p2;
                    } else {
                        float dsq = q0 * q0 + q1 * q1 + q2 * q2;
                        float cth = 0.8f * dot / (dsq + 1e-6f);
                        h0 = p0 - cth * q0; h1 = p1 - cth * q1; h2 = p2 - cth * q2;
                    }
                    h4s[(w * KC + kc) * Opad + lane * OPT + j] = make_float4(h0, h1, h2, 0.f);
                }
            }
        }
        __syncwarp();
        if (act) {
            float mv[OPT][KC][3];
#pragma unroll
            for (int j = 0; j < OPT; j++)
#pragma unroll
                for (int kc = 0; kc < KC; kc++) mv[j][kc][0] = mv[j][kc][1] = mv[j][kc][2] = 0.f;
#pragma unroll 2
            for (int c = 0; c < O; c++) {
                float wv[OPT];
#pragma unroll
                for (int j = 0; j < OPT; j++) wv[j] = WmT[c * Opad + lane * OPT + j];
#pragma unroll
                for (int kc = 0; kc < KC; kc++) {
                    float4 hc = h4s[(w * KC + kc) * Opad + c];
#pragma unroll
                    for (int j = 0; j < OPT; j++) {
                        mv[j][kc][0] += wv[j] * hc.x;
                        mv[j][kc][1] += wv[j] * hc.y;
                        mv[j][kc][2] += wv[j] * hc.z;
                    }
                }
            }
#pragma unroll
            for (int kc = 0; kc < KC; kc++) {
#pragma unroll
                for (int j = 0; j < OPT; j++) {
                    float4 hj = h4s[(w * KC + kc) * Opad + lane * OPT + j];
                    float pd = hj.x * mv[j][kc][0] + hj.y * mv[j][kc][1] + hj.z * mv[j][kc][2];
                    if (pd > best[j]) {
                        best[j] = pd;
                        bh[j][0] = hj.x; bh[j][1] = hj.y; bh[j][2] = hj.z;
                    }
                }
            }
        }
        __syncwarp();
    }

    if (act) {
#pragma unroll
        for (int j = 0; j < OPT; j++) {
            int o = lane * OPT + j;
            if (o < O) {
                float* op = out + (((size_t)b * O + o) * 3) * NN + n;
                op[0]      = bh[j][0];
                op[NN]     = bh[j][1];
                op[2 * NN] = bh[j][2];
            }
        }
    }
}

// ---------------- layer 5: vn_leaky on concat(x1..x4) -> (B,1023,N), NP=4 ----------------
__global__ void __launch_bounds__(352) layer5_kernel(const float* __restrict__ Wd5) {
    constexpr int NP = 4;
    __shared__ float4 es[NP][169];
    __shared__ float dvs[NP][4];

    int b = blockIdx.x / (NN / NP);
    int tile = blockIdx.x % (NN / NP);
    int t = threadIdx.x;

    for (int idx = t; idx < NP * 169; idx += 352) {
        int p = idx / 169, c = idx - p * 169;
        int n = tile * NP + p;
        const float* src; int cc, CL;
        if (c < 21)      { src = d_x1; cc = c;      CL = 21; }
        else if (c < 42) { src = d_x2; cc = c - 21; CL = 21; }
        else if (c < 84) { src = d_x3; cc = c - 42; CL = 42; }
        else             { src = d_x4; cc = c - 84; CL = 85; }
        size_t base = (((size_t)b * CL + cc) * 3) * NN + n;
        es[p][c] = make_float4(src[base], src[base + NN], src[base + 2 * NN], 0.f);
    }
    __syncthreads();

    if (t < NP) {
        int p = t;
        float s0 = 0.f, s1 = 0.f, s2 = 0.f;
        for (int c = 0; c < 169; c++) {
            float wv = Wd5[c];
            float4 e = es[p][c];
            s0 += wv * e.x; s1 += wv * e.y; s2 += wv * e.z;
        }
        dvs[p][0] = s0; dvs[p][1] = s1; dvs[p][2] = s2;
        dvs[p][3] = 0.8f / (s0 * s0 + s1 * s1 + s2 * s2 + 1e-6f);
    }
    __syncthreads();

    int o = t;
    if (o < 341) {
        float a[NP][3];
#pragma unroll
        for (int p = 0; p < NP; p++) a[p][0] = a[p][1] = a[p][2] = 0.f;
        const float* wc = d_wp5t + o;
#pragma unroll 2
        for (int c = 0; c < 169; c++) {
            float wv = wc[(size_t)c * 341];
#pragma unroll
            for (int p = 0; p < NP; p++) {
                float4 e = es[p][c];
                a[p][0] += wv * e.x; a[p][1] += wv * e.y; a[p][2] += wv * e.z;
            }
        }
#pragma unroll
        for (int p = 0; p < NP; p++) {
            int n = tile * NP + p;
            float dot = a[p][0] * dvs[p][0] + a[p][1] * dvs[p][1] + a[p][2] * dvs[p][2];
            float h0, h1, h2;
            if (dot >= 0.f) { h0 = a[p][0]; h1 = a[p][1]; h2 = a[p][2]; }
            else {
                float cth = dot * dvs[p][3];
                h0 = a[p][0] - cth * dvs[p][0];
                h1 = a[p][1] - cth * dvs[p][1];
                h2 = a[p][2] - cth * dvs[p][2];
            }
            size_t base = ((size_t)b * 1023 + o * 3) * NN + n;
            d_h5[base]          = h0;
            d_h5[base + NN]     = h1;
            d_h5[base + 2 * NN] = h2;
        }
    }
}

// ---------------- global max + mean over N: warp-per-channel, no block syncs ----------------
__global__ void __launch_bounds__(128) reduce_kernel() {
    int idx = blockIdx.x * 4 + (threadIdx.x >> 5);
    int lane = threadIdx.x & 31;
    int b = idx / 1023, ch = idx - b * 1023;
    const float* row = d_h5 + (size_t)b * 1023 * NN + (size_t)ch * NN;
    float mx = -CUDART_INF_F, sm = 0.f;
    for (int m = lane; m < NN; m += 32) {
        float v = row[m];
        mx = fmaxf(mx, v);
        sm += v;
    }
#pragma unroll
    for (int off = 16; off; off >>= 1) {
        mx = fmaxf(mx, __shfl_down_sync(0xffffffffu, mx, off));
        sm += __shfl_down_sync(0xffffffffu, sm, off);
    }
    if (lane == 0) {
        d_g[b * 2046 + ch]        = mx;
        d_g[b * 2046 + 1023 + ch] = sm * (1.f / NN);
    }
}

// ---------------- FC: one warp per output element, float2 loads ----------------
__global__ void fc_kernel(const float* __restrict__ in, const float* __restrict__ W,
                          const float* __restrict__ bias, float* __restrict__ out,
                          int rows, int icols, int ocols, float slope) {
    int gw = (blockIdx.x * blockDim.x + threadIdx.x) >> 5;
    int lane = threadIdx.x & 31;
    if (gw >= rows * ocols) return;
    int r = gw / ocols;
    int o = gw - r * ocols;
    const float2* ir = (const float2*)(in + (size_t)r * icols);
    const float2* wr = (const float2*)(W + (size_t)o * icols);
    int ic2 = icols >> 1;
    float s = 0.f;
    for (int c = lane; c < ic2; c += 32) {
        float2 a = ir[c], wv = wr[c];
        s += a.x * wv.x + a.y * wv.y;
    }
#pragma unroll
    for (int off = 16; off; off >>= 1) s += __shfl_down_sync(0xffffffffu, s, off);
    if (lane == 0) {
        s += bias[o];
        if (slope != 1.0f) s = (s >= 0.f) ? s : slope * s;
        out[(size_t)r * ocols + o] = s;
    }
}

// ---------------- launch ----------------
extern "C" void kernel_launch(void* const* d_in, const int* in_sizes, int n_in,
                              void* d_out, int out_size) {
    const float* x   = (const float*)d_in[0];
    const float* Wp1 = (const float*)d_in[1];
    const float* Wd1 = (const float*)d_in[2];
    const float* Wm1 = (const float*)d_in[3];
    const float* Wp2 = (const float*)d_in[4];
    const float* Wd2 = (const float*)d_in[5];
    const float* Wm2 = (const float*)d_in[6];
    const float* Wp3 = (const float*)d_in[7];
    const float* Wd3 = (const float*)d_in[8];
    const float* Wm3 = (const float*)d_in[9];
    const float* Wp4 = (const float*)d_in[10];
    const float* Wd4 = (const float*)d_in[11];
    const float* Wm4 = (const float*)d_in[12];
    const float* Wp5 = (const float*)d_in[13];
    const float* Wd5 = (const float*)d_in[14];
    const float* W1  = (const float*)d_in[15];
    const float* b1  = (const float*)d_in[16];
    const float* W2  = (const float*)d_in[17];
    const float* b2  = (const float*)d_in[18];
    const float* W3  = (const float*)d_in[19];
    const float* b3  = (const float*)d_in[20];

    float *f0, *x1, *x2, *x3, *x4, *pad, *ctrb, *g, *g1, *g2;
    cudaGetSymbolAddress((void**)&f0,   d_f0);
    cudaGetSymbolAddress((void**)&x1,   d_x1);
    cudaGetSymbolAddress((void**)&x2,   d_x2);
    cudaGetSymbolAddress((void**)&x3,   d_x3);
    cudaGetSymbolAddress((void**)&x4,   d_x4);
    cudaGetSymbolAddress((void**)&pad,  d_pad);
    cudaGetSymbolAddress((void**)&ctrb, d_ctr);
    cudaGetSymbolAddress((void**)&g,    d_g);
    cudaGetSymbolAddress((void**)&g1,   d_g1);
    cudaGetSymbolAddress((void**)&g2,   d_g2);

    // dynamic smem for edge_combine: h4s (NP*4*Opad float4) + WmT (O*Opad) + kk (NP*20 int)
    const int sz12 = 16 * 4 * 21 * 16 + 21 * 21 * 4 + 16 * KK * 4;  // 24548 (NP=16)
    const int sz3  = 8 * 4 * 42 * 16 + 42 * 42 * 4 + 8 * KK * 4;    // 29200 (NP=8)
    const int sz4  = 8 * 4 * 87 * 16 + 85 * 87 * 4 + 8 * KK * 4;    // 74764 (NP=8, >48KB)
    cudaFuncSetAttribute(edge_combine<85, 3, 8>, cudaFuncAttributeMaxDynamicSharedMemorySize, sz4);

    prep_kernel<<<(341 * 169 + 255) / 256, 256>>>(x, Wp5, Wp1, Wd1, Wp2, Wd2, Wp3, Wd3, Wp4, Wd4);

    sq_kernel<3><<<BB * NN / 256, 256>>>(f0);
    knn_kernel<3><<<BB * NN / 4, 256>>>(f0);
    gemm2<1, 21, 2, 0><<<dim3(BB * (NN / 32), 2), 96>>>(f0, pad, ctrb);
    edge_combine<21, 1, 16><<<BB * NN / 16, 512, sz12>>>(pad, ctrb, Wm1, x1);

    sq_kernel<63><<<BB * NN / 256, 256>>>(x1);
    knn_kernel<63><<<BB * NN / 4, 256>>>(x1);
    gemm2<21, 21, 2, 42><<<dim3(BB * (NN / 32), 2), 96>>>(x1, pad, ctrb);
    edge_combine<21, 1, 16><<<BB * NN / 16, 512, sz12>>>(pad, ctrb, Wm2, x2);

    sq_kernel<63><<<BB * NN / 256, 256>>>(x2);
    knn_kernel<63><<<BB * NN / 4, 256>>>(x2);
    gemm2<21, 42, 6, 504><<<dim3(BB * (NN / 32), 6), 96>>>(x2, pad, ctrb);
    edge_combine<42, 2, 8><<<BB * NN / 8, 256, sz3>>>(pad, ctrb, Wm3, x3);

    sq_kernel<126><<<BB * NN / 256, 256>>>(x3);
    knn_kernel<126><<<BB * NN / 4, 256>>>(x3);
    gemm2<42, 85, 11, 1428><<<dim3(BB * (NN / 32), 11), 96>>>(x3, pad, ctrb);
    edge_combine<85, 3, 8><<<BB * NN / 8, 256, sz4>>>(pad, ctrb, Wm4, x4);

    layer5_kernel<<<BB * NN / 4, 352>>>(Wd5);
    reduce_kernel<<<BB * 1023 / 4, 128>>>();

    fc_kernel<<<(8 * 512 * 32 + 255) / 256, 256>>>(g,  W1, b1, g1, 8, 2046, 512, 0.01f);
    fc_kernel<<<(8 * 256 * 32 + 255) / 256, 256>>>(g1, W2, b2, g2, 8, 512,  256, 0.01f);
    fc_kernel<<<(8 * 128 * 32 + 255) / 256, 256>>>(g2, W3, b3, (float*)d_out, 8, 256, 128, 1.0f);
}

// round 16
// speedup vs baseline: 1.0215x; 1.0215x over previous
#include <cuda_runtime.h>
#include <math_constants.h>

#define BB 8
#define NN 1024
#define KK 20

typedef unsigned long long ull;

// ---------------- scratch (device globals: no allocation allowed) ----------------
__device__ float d_f0[BB * 3 * NN];            // (B,3,N)
__device__ float d_x1[BB * 21 * 3 * NN];
__device__ float d_x2[BB * 21 * 3 * NN];
__device__ float d_x3[BB * 42 * 3 * NN];
__device__ float d_x4[BB * 85 * 3 * NN];
__device__ int   d_knnIdx[BB * NN * KK];
__device__ float d_pad[BB * NN * 85 * 8 + 16];  // per-point, layout (B,N,O,8): [pa0,da0,pa1,da1,pa2,da2,-,-]
__device__ float d_ctr[BB * NN * 85 * 8 + 16];  // per-point (pb,db) same layout
__device__ float4 d_w4[4998];                   // interleaved [ap,bp,ad,bd] for layers 1..4
__device__ float d_wp5t[169 * 341];
__device__ float d_h5[BB * 1023 * NN];
__device__ float d_g [BB * 2046];
__device__ float d_g1[BB * 512];
__device__ float d_g2[BB * 256];

// ---------------- fused prep: x transpose + Wp5 transpose + w4 table ----------------
__global__ void prep_kernel(const float* __restrict__ x, const float* __restrict__ Wp5,
                            const float* __restrict__ Wp1, const float* __restrict__ Wd1,
                            const float* __restrict__ Wp2, const float* __restrict__ Wd2,
                            const float* __restrict__ Wp3, const float* __restrict__ Wd3,
                            const float* __restrict__ Wp4, const float* __restrict__ Wd4) {
    int i = blockIdx.x * 256 + threadIdx.x;

    if (i < BB * NN * 3) {
        int b = i / (NN * 3);
        int r = i - b * (NN * 3);
        int n = r / 3;
        int j = r - n * 3;
        d_f0[((size_t)b * 3 + j) * NN + n] = x[i];
    }
    if (i < 341 * 169) {
        int o = i / 169, c = i - o * 169;
        d_wp5t[c * 341 + o] = Wp5[i];
    }
    if (i < 4998) {
        const float *Wp, *Wd; int C, Cp, rel;
        if (i < 42)        { Wp = Wp1; Wd = Wd1; C = 1;  Cp = 2;  rel = i; }
        else if (i < 504)  { Wp = Wp2; Wd = Wd2; C = 21; Cp = 22; rel = i - 42; }
        else if (i < 1428) { Wp = Wp3; Wd = Wd3; C = 21; Cp = 22; rel = i - 504; }
        else               { Wp = Wp4; Wd = Wd4; C = 42; Cp = 42; rel = i - 1428; }
        int o = rel / Cp, c = rel - o * Cp;
        float ap = 0.f, bp = 0.f, ad = 0.f, bd = 0.f;
        if (c < C) {
            float wl = Wp[o * 2 * C + c], wr = Wp[o * 2 * C + C + c];
            ap = wl; bp = wr - wl;
            wl = Wd[o * 2 * C + c]; wr = Wd[o * 2 * C + C + c];
            ad = wl; bd = wr - wl;
        }
        d_w4[i] = make_float4(ap, bp, ad, bd);
    }
}

// ---------------- KNN with fused sq: warp-local top-20 then single merge ----------------
template <int D>
__global__ void __launch_bounds__(256) knn_kernel(const float* __restrict__ feat) {
    constexpr int NB = 4;
    int b = blockIdx.x / (NN / NB);
    int tile = blockIdx.x % (NN / NB);
    const float* f = feat + (size_t)b * D * NN;

    __shared__ float4 ctr4[D];
    __shared__ ull    lists[NB][8 * KK];
    __shared__ float4 sqsh;

    int t = threadIdx.x, lane = t & 31, wid = t >> 5;
    int nb0 = tile * NB;

    for (int d = t; d < D; d += 256)
        ctr4[d] = make_float4(f[(size_t)d * NN + nb0],     f[(size_t)d * NN + nb0 + 1],
                              f[(size_t)d * NN + nb0 + 2], f[(size_t)d * NN + nb0 + 3]);
    __syncthreads();

    float acc[NB][4];
#pragma unroll
    for (int r = 0; r < NB; r++)
#pragma unroll
        for (int j = 0; j < 4; j++) acc[r][j] = 0.f;
    float sq0 = 0.f, sq1 = 0.f, sq2 = 0.f, sq3 = 0.f;

    const float4* fp = (const float4*)(f) + t;
#pragma unroll 4
    for (int d = 0; d < D; d++) {
        float4 v = fp[(size_t)d * (NN / 4)];
        float4 c = ctr4[d];
        sq0 += v.x * v.x; sq1 += v.y * v.y; sq2 += v.z * v.z; sq3 += v.w * v.w;
        acc[0][0] += c.x * v.x; acc[0][1] += c.x * v.y; acc[0][2] += c.x * v.z; acc[0][3] += c.x * v.w;
        acc[1][0] += c.y * v.x; acc[1][1] += c.y * v.y; acc[1][2] += c.y * v.z; acc[1][3] += c.y * v.w;
        acc[2][0] += c.z * v.x; acc[2][1] += c.z * v.y; acc[2][2] += c.z * v.z; acc[2][3] += c.z * v.w;
        acc[3][0] += c.w * v.x; acc[3][1] += c.w * v.y; acc[3][2] += c.w * v.z; acc[3][3] += c.w * v.w;
    }

    if (t == tile) sqsh = make_float4(sq0, sq1, sq2, sq3);
    __syncthreads();
    float sqn[NB] = { sqsh.x, sqsh.y, sqsh.z, sqsh.w };
    float sqj[4]  = { sq0, sq1, sq2, sq3 };

    ull cand[NB][4];
#pragma unroll
    for (int r = 0; r < NB; r++) {
#pragma unroll
        for (int j = 0; j < 4; j++) {
            float dv = 2.f * acc[r][j] - sqn[r] - sqj[j];
            unsigned bits = __float_as_uint(dv);
            unsigned key = (bits & 0x80000000u) ? ~bits : (bits | 0x80000000u);
            int m = 4 * t + j;
            cand[r][j] = ((ull)key << 10) | (unsigned)(1023 - m);
        }
        ull c0 = cand[r][0], c1 = cand[r][1], c2 = cand[r][2], c3 = cand[r][3], tmp;
        if (c1 > c0) { tmp = c0; c0 = c1; c1 = tmp; }
        if (c3 > c2) { tmp = c2; c2 = c3; c3 = tmp; }
        if (c2 > c0) { tmp = c0; c0 = c2; c2 = tmp; }
        if (c3 > c1) { tmp = c1; c1 = c3; c3 = tmp; }
        if (c2 > c1) { tmp = c1; c1 = c2; c2 = tmp; }
        cand[r][0] = c0; cand[r][1] = c1; cand[r][2] = c2; cand[r][3] = c3;
    }

    int ptr[NB] = {0, 0, 0, 0};
    for (int k = 0; k < KK; k++) {
#pragma unroll
        for (int r = 0; r < NB; r++) {
            int p = ptr[r];
            ull h = (p == 0) ? cand[r][0] : (p == 1) ? cand[r][1]
                  : (p == 2) ? cand[r][2] : (p == 3) ? cand[r][3] : 0ULL;
            unsigned hk = (unsigned)(h >> 10);
            unsigned wm = __reduce_max_sync(0xffffffffu, hk);
            unsigned bal = __ballot_sync(0xffffffffu, hk == wm);
            if (lane == __ffs(bal) - 1) {
                lists[r][wid * KK + k] = h;
                ptr[r] = p + 1;
            }
        }
    }
    __syncthreads();

    if (wid < NB) {
        int r = wid;
        ull c5[5];
#pragma unroll
        for (int j = 0; j < 5; j++) c5[j] = lists[r][j * 32 + lane];
        ull tmp;
#define CASD(a, bq) { if (c5[bq] > c5[a]) { tmp = c5[a]; c5[a] = c5[bq]; c5[bq] = tmp; } }
        CASD(0, 1) CASD(3, 4) CASD(2, 4) CASD(2, 3) CASD(1, 4)
        CASD(0, 3) CASD(0, 2) CASD(1, 3) CASD(1, 2)
#undef CASD
        int p = 0;
        size_t ob = ((size_t)b * NN + nb0 + r) * KK;
        for (int k = 0; k < KK; k++) {
            ull h = (p == 0) ? c5[0] : (p == 1) ? c5[1] : (p == 2) ? c5[2]
                  : (p == 3) ? c5[3] : (p == 4) ? c5[4] : 0ULL;
            unsigned hk = (unsigned)(h >> 10);
            unsigned gm = __reduce_max_sync(0xffffffffu, hk);
            unsigned tv = (hk == gm) ? (unsigned)(h & 1023ULL) : 0u;
            unsigned gt = __reduce_max_sync(0xffffffffu, tv);
            unsigned bal = __ballot_sync(0xffffffffu, (hk == gm) && (tv == gt));
            if (lane == __ffs(bal) - 1) {
                d_knnIdx[ob + k] = 1023 - (int)(h & 1023ULL);
                p++;
            }
        }
    }
}

// ---------------- per-point GEMM v2 (layers 2-4) ----------------
template <int C, int O, int OG, int WOFF>
__global__ void __launch_bounds__(96) gemm2(const float* __restrict__ x,
                                            float* __restrict__ pad,
                                            float* __restrict__ ctrb) {
    constexpr int Cp = (C + 1) & ~1;
    constexpr int OC = (O + OG - 1) / OG;
    int b = blockIdx.x / (NN / 32);
    int tile = blockIdx.x % (NN / 32);
    int og = blockIdx.y;
    int t = threadIdx.x;
    int n = tile * 32 + (t & 31);
    int ax = t >> 5;

    float xr[Cp];
#pragma unroll
    for (int c = 0; c < C; c++)
        xr[c] = x[(((size_t)b * C + c) * 3 + ax) * NN + n];
    if (Cp > C) xr[Cp - 1] = 0.f;

    int o0 = og * OC;
    int o1 = (o0 + OC < O) ? o0 + OC : O;
    const float4* W4 = d_w4 + WOFF;
    size_t obase = (size_t)(b * NN + n) * (O * 8) + ax * 2;

    for (int o = o0; o < o1; o++) {
        float pa = 0.f, pb = 0.f, da = 0.f, db = 0.f;
#pragma unroll
        for (int cc = 0; cc < Cp; cc += 2) {
            float4 w0 = W4[o * Cp + cc];
            float4 w1 = W4[o * Cp + cc + 1];
            float x0 = xr[cc], x1v = xr[cc + 1];
            pa += w0.x * x0 + w1.x * x1v;
            pb += w0.y * x0 + w1.y * x1v;
            da += w0.z * x0 + w1.z * x1v;
            db += w0.w * x0 + w1.w * x1v;
        }
        *(float2*)&pad[obase + o * 8]  = make_float2(pa, da);
        *(float2*)&ctrb[obase + o * 8] = make_float2(pb, db);
    }
}

// ---------------- layer-1 fused combine: C=1, weights applied inline ----------------
template <int NP>
__global__ void __launch_bounds__(32 * NP) edge_combine1(const float* __restrict__ f0,
                                                         const float* __restrict__ Wm,
                                                         float* __restrict__ out) {
    constexpr int O = 21, AT = 21, Opad = 21, KC = 4, T = 32 * NP;
    extern __shared__ float4 sm4[];
    float4* h4s = sm4;                              // NP*KC*Opad float4
    float*  WmT = (float*)(sm4 + NP * KC * Opad);   // O*Opad floats
    int*    kk  = (int*)(WmT + O * Opad);           // NP*KK ints

    int b = blockIdx.x / (NN / NP);
    int ptile = blockIdx.x % (NN / NP);
    int t = threadIdx.x;
    int w = t >> 5, lane = t & 31;

    for (int i = t; i < O * O; i += T) {
        int o = i / O, c = i - o * O;
        WmT[c * Opad + o] = Wm[i];
    }
    int n = ptile * NP + w;
    if (lane < KK) kk[w * KK + lane] = d_knnIdx[((size_t)b * NN + n) * KK + lane];
    __syncthreads();

    bool act = lane < AT;
    const float* fb = f0 + (size_t)b * 3 * NN;
    float xn0 = fb[n], xn1 = fb[NN + n], xn2 = fb[2 * NN + n];
    float4 w4 = act ? d_w4[lane * 2] : make_float4(0.f, 0.f, 0.f, 0.f);
    // pb = RN(bp*xn), db = RN(bd*xn) — matches old gemm2 output exactly
    float pb0 = __fmul_rn(w4.y, xn0), pb1 = __fmul_rn(w4.y, xn1), pb2 = __fmul_rn(w4.y, xn2);
    float db0 = __fmul_rn(w4.w, xn0), db1 = __fmul_rn(w4.w, xn1), db2 = __fmul_rn(w4.w, xn2);

    float best = -CUDART_INF_F;
    float bh[3] = {0.f, 0.f, 0.f};

    for (int chunk = 0; chunk < KK / KC; chunk++) {
#pragma unroll
        for (int kc = 0; kc < KC; kc++) {
            int m = kk[w * KK + chunk * KC + kc];
            float xm0 = fb[m], xm1 = fb[NN + m], xm2 = fb[2 * NN + m];
            if (act) {
                // pa = RN(ap*xm); p = RN(pa+pb) — matches old ADD path
                float pa0 = __fmul_rn(w4.x, xm0), qa0 = __fmul_rn(w4.z, xm0);
                float pa1 = __fmul_rn(w4.x, xm1), qa1 = __fmul_rn(w4.z, xm1);
                float pa2 = __fmul_rn(w4.x, xm2), qa2 = __fmul_rn(w4.z, xm2);
                float p0 = __fadd_rn(pa0, pb0), q0 = __fadd_rn(qa0, db0);
                float p1 = __fadd_rn(pa1, pb1), q1 = __fadd_rn(qa1, db1);
                float p2 = __fadd_rn(pa2, pb2), q2 = __fadd_rn(qa2, db2);
                float dot = p0 * q0 + p1 * q1 + p2 * q2;
                float h0, h1, h2;
                if (dot >= 0.f) {
                    h0 = p0; h1 = p1; h2 = p2;
                } else {
                    float dsq = q0 * q0 + q1 * q1 + q2 * q2;
                    float cth = 0.8f * dot / (dsq + 1e-6f);
                    h0 = p0 - cth * q0; h1 = p1 - cth * q1; h2 = p2 - cth * q2;
                }
                h4s[(w * KC + kc) * Opad + lane] = make_float4(h0, h1, h2, 0.f);
            }
        }
        __syncwarp();
        if (act) {
            float mv[KC][3];
#pragma unroll
            for (int kc = 0; kc < KC; kc++) mv[kc][0] = mv[kc][1] = mv[kc][2] = 0.f;
#pragma unroll 2
            for (int c = 0; c < O; c++) {
                float wv = WmT[c * Opad + lane];
#pragma unroll
                for (int kc = 0; kc < KC; kc++) {
                    float4 hc = h4s[(w * KC + kc) * Opad + c];
                    mv[kc][0] += wv * hc.x;
                    mv[kc][1] += wv * hc.y;
                    mv[kc][2] += wv * hc.z;
                }
            }
#pragma unroll
            for (int kc = 0; kc < KC; kc++) {
                float4 hj = h4s[(w * KC + kc) * Opad + lane];
                float pd = hj.x * mv[kc][0] + hj.y * mv[kc][1] + hj.z * mv[kc][2];
                if (pd > best) {
                    best = pd;
                    bh[0] = hj.x; bh[1] = hj.y; bh[2] = hj.z;
                }
            }
        }
        __syncwarp();
    }

    if (act) {
        float* op = out + (((size_t)b * O + lane) * 3) * NN + n;
        op[0]      = bh[0];
        op[NN]     = bh[1];
        op[2 * NN] = bh[2];
    }
}

// ---------------- edge combine + leaky + learned max-pool (layers 2-4) ----------------
template <int O, int OPT, int NP>
__global__ void __launch_bounds__(32 * NP) edge_combine(const float* __restrict__ pad,
                                                        const float* __restrict__ ctrb,
                                                        const float* __restrict__ Wm,
                                                        float* __restrict__ out) {
    constexpr int AT = (O + OPT - 1) / OPT;
    constexpr int Opad = AT * OPT;
    constexpr int KC = 4;
    constexpr int T = 32 * NP;

    extern __shared__ float4 sm4[];
    float4* h4s = sm4;
    float*  WmT = (float*)(sm4 + NP * KC * Opad);
    int*    kk  = (int*)(WmT + O * Opad);

    int b = blockIdx.x / (NN / NP);
    int ptile = blockIdx.x % (NN / NP);
    int t = threadIdx.x;
    int w = t >> 5, lane = t & 31;

    for (int i = t; i < O * O; i += T) {
        int o = i / O, c = i - o * O;
        WmT[c * Opad + o] = Wm[i];
    }
    if constexpr (Opad > O) {
        for (int i = t; i < O * (Opad - O); i += T) {
            int c = i / (Opad - O), j = i - c * (Opad - O);
            WmT[c * Opad + O + j] = 0.f;
        }
    }
    int n = ptile * NP + w;
    if (lane < KK) kk[w * KK + lane] = d_knnIdx[((size_t)b * NN + n) * KK + lane];
    __syncthreads();

    bool act = lane < AT;
    float pb[OPT][3], db[OPT][3];
    size_t cbase = (size_t)(b * NN + n) * (O * 8);
    if (act) {
#pragma unroll
        for (int j = 0; j < OPT; j++) {
            int o = lane * OPT + j;
            float4 u  = *(const float4*)&ctrb[cbase + o * 8];
            float2 u2 = *(const float2*)&ctrb[cbase + o * 8 + 4];
            pb[j][0] = u.x;  db[j][0] = u.y;
            pb[j][1] = u.z;  db[j][1] = u.w;
            pb[j][2] = u2.x; db[j][2] = u2.y;
        }
    }

    float best[OPT];
    float bh[OPT][3];
#pragma unroll
    for (int j = 0; j < OPT; j++) { best[j] = -CUDART_INF_F; bh[j][0] = bh[j][1] = bh[j][2] = 0.f; }

    for (int chunk = 0; chunk < KK / KC; chunk++) {
#pragma unroll
        for (int kc = 0; kc < KC; kc++) {
            int m = kk[w * KK + chunk * KC + kc];
            if (act) {
                size_t gbase = (size_t)(b * NN + m) * (O * 8);
#pragma unroll
                for (int j = 0; j < OPT; j++) {
                    int o = lane * OPT + j;
                    float4 u  = *(const float4*)&pad[gbase + o * 8];
                    float2 u2 = *(const float2*)&pad[gbase + o * 8 + 4];
                    float p0 = u.x  + pb[j][0], q0 = u.y  + db[j][0];
                    float p1 = u.z  + pb[j][1], q1 = u.w  + db[j][1];
                    float p2 = u2.x + pb[j][2], q2 = u2.y + db[j][2];
                    float dot = p0 * q0 + p1 * q1 + p2 * q2;
                    float h0, h1, h2;
                    if (dot >= 0.f) {
                        h0 = p0; h1 = p1; h2 = p2;
                    } else {
                        float dsq = q0 * q0 + q1 * q1 + q2 * q2;
                        float cth = 0.8f * dot / (dsq + 1e-6f);
                        h0 = p0 - cth * q0; h1 = p1 - cth * q1; h2 = p2 - cth * q2;
                    }
                    h4s[(w * KC + kc) * Opad + lane * OPT + j] = make_float4(h0, h1, h2, 0.f);
                }
            }
        }
        __syncwarp();
        if (act) {
            float mv[OPT][KC][3];
#pragma unroll
            for (int j = 0; j < OPT; j++)
#pragma unroll
                for (int kc = 0; kc < KC; kc++) mv[j][kc][0] = mv[j][kc][1] = mv[j][kc][2] = 0.f;
#pragma unroll 2
            for (int c = 0; c < O; c++) {
                float wv[OPT];
#pragma unroll
                for (int j = 0; j < OPT; j++) wv[j] = WmT[c * Opad + lane * OPT + j];
#pragma unroll
                for (int kc = 0; kc < KC; kc++) {
                    float4 hc = h4s[(w * KC + kc) * Opad + c];
#pragma unroll
                    for (int j = 0; j < OPT; j++) {
                        mv[j][kc][0] += wv[j] * hc.x;
                        mv[j][kc][1] += wv[j] * hc.y;
                        mv[j][kc][2] += wv[j] * hc.z;
                    }
                }
            }
#pragma unroll
            for (int kc = 0; kc < KC; kc++) {
#pragma unroll
                for (int j = 0; j < OPT; j++) {
                    float4 hj = h4s[(w * KC + kc) * Opad + lane * OPT + j];
                    float pd = hj.x * mv[j][kc][0] + hj.y * mv[j][kc][1] + hj.z * mv[j][kc][2];
                    if (pd > best[j]) {
                        best[j] = pd;
                        bh[j][0] = hj.x; bh[j][1] = hj.y; bh[j][2] = hj.z;
                    }
                }
            }
        }
        __syncwarp();
    }

    if (act) {
#pragma unroll
        for (int j = 0; j < OPT; j++) {
            int o = lane * OPT + j;
            if (o < O) {
                float* op = out + (((size_t)b * O + o) * 3) * NN + n;
                op[0]      = bh[j][0];
                op[NN]     = bh[j][1];
                op[2 * NN] = bh[j][2];
            }
        }
    }
}

// ---------------- layer 5: vn_leaky on concat(x1..x4) -> (B,1023,N), NP=4 ----------------
__global__ void __launch_bounds__(352) layer5_kernel(const float* __restrict__ Wd5) {
    constexpr int NP = 4;
    __shared__ float4 es[NP][169];
    __shared__ float dvs[NP][4];

    int b = blockIdx.x / (NN / NP);
    int tile = blockIdx.x % (NN / NP);
    int t = threadIdx.x;

    for (int idx = t; idx < NP * 169; idx += 352) {
        int p = idx / 169, c = idx - p * 169;
        int n = tile * NP + p;
        const float* src; int cc, CL;
        if (c < 21)      { src = d_x1; cc = c;      CL = 21; }
        else if (c < 42) { src = d_x2; cc = c - 21; CL = 21; }
        else if (c < 84) { src = d_x3; cc = c - 42; CL = 42; }
        else             { src = d_x4; cc = c - 84; CL = 85; }
        size_t base = (((size_t)b * CL + cc) * 3) * NN + n;
        es[p][c] = make_float4(src[base], src[base + NN], src[base + 2 * NN], 0.f);
    }
    __syncthreads();

    if (t < NP) {
        int p = t;
        float s0 = 0.f, s1 = 0.f, s2 = 0.f;
        for (int c = 0; c < 169; c++) {
            float wv = Wd5[c];
            float4 e = es[p][c];
            s0 += wv * e.x; s1 += wv * e.y; s2 += wv * e.z;
        }
        dvs[p][0] = s0; dvs[p][1] = s1; dvs[p][2] = s2;
        dvs[p][3] = 0.8f / (s0 * s0 + s1 * s1 + s2 * s2 + 1e-6f);
    }
    __syncthreads();

    int o = t;
    if (o < 341) {
        float a[NP][3];
#pragma unroll
        for (int p = 0; p < NP; p++) a[p][0] = a[p][1] = a[p][2] = 0.f;
        const float* wc = d_wp5t + o;
#pragma unroll 2
        for (int c = 0; c < 169; c++) {
            float wv = wc[(size_t)c * 341];
#pragma unroll
            for (int p = 0; p < NP; p++) {
                float4 e = es[p][c];
                a[p][0] += wv * e.x; a[p][1] += wv * e.y; a[p][2] += wv * e.z;
            }
        }
#pragma unroll
        for (int p = 0; p < NP; p++) {
            int n = tile * NP + p;
            float dot = a[p][0] * dvs[p][0] + a[p][1] * dvs[p][1] + a[p][2] * dvs[p][2];
            float h0, h1, h2;
            if (dot >= 0.f) { h0 = a[p][0]; h1 = a[p][1]; h2 = a[p][2]; }
            else {
                float cth = dot * dvs[p][3];
                h0 = a[p][0] - cth * dvs[p][0];
                h1 = a[p][1] - cth * dvs[p][1];
                h2 = a[p][2] - cth * dvs[p][2];
            }
            size_t base = ((size_t)b * 1023 + o * 3) * NN + n;
            d_h5[base]          = h0;
            d_h5[base + NN]     = h1;
            d_h5[base + 2 * NN] = h2;
        }
    }
}

// ---------------- global max + mean over N: warp-per-channel ----------------
__global__ void __launch_bounds__(128) reduce_kernel() {
    int idx = blockIdx.x * 4 + (threadIdx.x >> 5);
    int lane = threadIdx.x & 31;
    int b = idx / 1023, ch = idx - b * 1023;
    const float* row = d_h5 + (size_t)b * 1023 * NN + (size_t)ch * NN;
    float mx = -CUDART_INF_F, sm = 0.f;
    for (int m = lane; m < NN; m += 32) {
        float v = row[m];
        mx = fmaxf(mx, v);
        sm += v;
    }
#pragma unroll
    for (int off = 16; off; off >>= 1) {
        mx = fmaxf(mx, __shfl_down_sync(0xffffffffu, mx, off));
        sm += __shfl_down_sync(0xffffffffu, sm, off);
    }
    if (lane == 0) {
        d_g[b * 2046 + ch]        = mx;
        d_g[b * 2046 + 1023 + ch] = sm * (1.f / NN);
    }
}

// ---------------- FC: one warp per output element, float2 loads ----------------
__global__ void fc_kernel(const float* __restrict__ in, const float* __restrict__ W,
                          const float* __restrict__ bias, float* __restrict__ out,
                          int rows, int icols, int ocols, float slope) {
    int gw = (blockIdx.x * blockDim.x + threadIdx.x) >> 5;
    int lane = threadIdx.x & 31;
    if (gw >= rows * ocols) return;
    int r = gw / ocols;
    int o = gw - r * ocols;
    const float2* ir = (const float2*)(in + (size_t)r * icols);
    const float2* wr = (const float2*)(W + (size_t)o * icols);
    int ic2 = icols >> 1;
    float s = 0.f;
    for (int c = lane; c < ic2; c += 32) {
        float2 a = ir[c], wv = wr[c];
        s += a.x * wv.x + a.y * wv.y;
    }
#pragma unroll
    for (int off = 16; off; off >>= 1) s += __shfl_down_sync(0xffffffffu, s, off);
    if (lane == 0) {
        s += bias[o];
        if (slope != 1.0f) s = (s >= 0.f) ? s : slope * s;
        out[(size_t)r * ocols + o] = s;
    }
}

// ---------------- launch ----------------
extern "C" void kernel_launch(void* const* d_in, const int* in_sizes, int n_in,
                              void* d_out, int out_size) {
    const float* x   = (const float*)d_in[0];
    const float* Wp1 = (const float*)d_in[1];
    const float* Wd1 = (const float*)d_in[2];
    const float* Wm1 = (const float*)d_in[3];
    const float* Wp2 = (const float*)d_in[4];
    const float* Wd2 = (const float*)d_in[5];
    const float* Wm2 = (const float*)d_in[6];
    const float* Wp3 = (const float*)d_in[7];
    const float* Wd3 = (const float*)d_in[8];
    const float* Wm3 = (const float*)d_in[9];
    const float* Wp4 = (const float*)d_in[10];
    const float* Wd4 = (const float*)d_in[11];
    const float* Wm4 = (const float*)d_in[12];
    const float* Wp5 = (const float*)d_in[13];
    const float* Wd5 = (const float*)d_in[14];
    const float* W1  = (const float*)d_in[15];
    const float* b1  = (const float*)d_in[16];
    const float* W2  = (const float*)d_in[17];
    const float* b2  = (const float*)d_in[18];
    const float* W3  = (const float*)d_in[19];
    const float* b3  = (const float*)d_in[20];

    float *f0, *x1, *x2, *x3, *x4, *pad, *ctrb, *g, *g1, *g2;
    cudaGetSymbolAddress((void**)&f0,   d_f0);
    cudaGetSymbolAddress((void**)&x1,   d_x1);
    cudaGetSymbolAddress((void**)&x2,   d_x2);
    cudaGetSymbolAddress((void**)&x3,   d_x3);
    cudaGetSymbolAddress((void**)&x4,   d_x4);
    cudaGetSymbolAddress((void**)&pad,  d_pad);
    cudaGetSymbolAddress((void**)&ctrb, d_ctr);
    cudaGetSymbolAddress((void**)&g,    d_g);
    cudaGetSymbolAddress((void**)&g1,   d_g1);
    cudaGetSymbolAddress((void**)&g2,   d_g2);

    // dynamic smem: h4s (NP*4*Opad float4) + WmT (O*Opad) + kk (NP*20 int)
    const int sz1  = 16 * 4 * 21 * 16 + 21 * 21 * 4 + 16 * KK * 4;  // 24548 (NP=16, layer1 fused)
    const int sz2  = 16 * 4 * 21 * 16 + 21 * 21 * 4 + 16 * KK * 4;  // 24548 (NP=16)
    const int sz3  = 8 * 4 * 42 * 16 + 42 * 42 * 4 + 8 * KK * 4;    // 29200 (NP=8)
    const int sz4  = 8 * 4 * 87 * 16 + 85 * 87 * 4 + 8 * KK * 4;    // 74764 (NP=8, >48KB)
    cudaFuncSetAttribute(edge_combine<85, 3, 8>, cudaFuncAttributeMaxDynamicSharedMemorySize, sz4);

    prep_kernel<<<(341 * 169 + 255) / 256, 256>>>(x, Wp5, Wp1, Wd1, Wp2, Wd2, Wp3, Wd3, Wp4, Wd4);

    knn_kernel<3><<<BB * NN / 4, 256>>>(f0);
    edge_combine1<16><<<BB * NN / 16, 512, sz1>>>(f0, Wm1, x1);

    knn_kernel<63><<<BB * NN / 4, 256>>>(x1);
    gemm2<21, 21, 2, 42><<<dim3(BB * (NN / 32), 2), 96>>>(x1, pad, ctrb);
    edge_combine<21, 1, 16><<<BB * NN / 16, 512, sz2>>>(pad, ctrb, Wm2, x2);

    knn_kernel<63><<<BB * NN / 4, 256>>>(x2);
    gemm2<21, 42, 6, 504><<<dim3(BB * (NN / 32), 6), 96>>>(x2, pad, ctrb);
    edge_combine<42, 2, 8><<<BB * NN / 8, 256, sz3>>>(pad, ctrb, Wm3, x3);

    knn_kernel<126><<<BB * NN / 4, 256>>>(x3);
    gemm2<42, 85, 11, 1428><<<dim3(BB * (NN / 32), 11), 96>>>(x3, pad, ctrb);
    edge_combine<85, 3, 8><<<BB * NN / 8, 256, sz4>>>(pad, ctrb, Wm4, x4);

    layer5_kernel<<<BB * NN / 4, 352>>>(Wd5);
    reduce_kernel<<<BB * 1023 / 4, 128>>>();

    fc_kernel<<<(8 * 512 * 32 + 255) / 256, 256>>>(g,  W1, b1, g1, 8, 2046, 512, 0.01f);
    fc_kernel<<<(8 * 256 * 32 + 255) / 256, 256>>>(g1, W2, b2, g2, 8, 512,  256, 0.01f);
    fc_kernel<<<(8 * 128 * 32 + 255) / 256, 256>>>(g2, W3, b3, (float*)d_out, 8, 256, 128, 1.0f);
}